// round 8
// baseline (speedup 1.0000x reference)
#include <cuda_runtime.h>

// Fixed shapes from setup_inputs
#define HH 100
#define WW 152
#define NPAIR 76           // WW/2
#define HWP 15200          // HH*WW
#define NCH 8
#define NPARAMS 169
#define MAXINST 400
#define OH 200
#define OW 304
#define ROWS_OUT 12        // output-logit rows per block
#define TPB 256

typedef unsigned long long u64;

__device__ __forceinline__ u64 pk2(float a, float b) {
    u64 r;
    asm("mov.b64 %0, {%1,%2};" : "=l"(r) : "r"(__float_as_uint(a)), "r"(__float_as_uint(b)));
    return r;
}
__device__ __forceinline__ void upk2(float& a, float& b, u64 x) {
    unsigned int lo, hi;
    asm("mov.b64 {%0,%1}, %2;" : "=r"(lo), "=r"(hi) : "l"(x));
    a = __uint_as_float(lo); b = __uint_as_float(hi);
}
__device__ __forceinline__ u64 ffma2(u64 a, u64 b, u64 c) {
    u64 d;
    asm("fma.rn.f32x2 %0, %1, %2, %3;" : "=l"(d) : "l"(a), "l"(b), "l"(c));
    return d;
}
__device__ __forceinline__ u64 relu2(u64 x) {
    float a, b; upk2(a, b, x);
    a = fmaxf(a, 0.0f); b = fmaxf(b, 0.0f);
    return pk2(a, b);
}

// ---------------------------------------------------------------------------
// Fused kernel: per (instance, 12-row stripe) block.
// Phase 1: 3-layer 1x1-conv MLP -> logits tile in smem (1 halo row), ONE
//          pixel-pair per thread per iteration (low register pressure).
// Phase 2: aligned_bilinear x2 stencil from smem -> float4 output stores.
// min 3 blocks/SM pinned: keeps regs <= 84 (no spills) and 24 warps/SM.
// ---------------------------------------------------------------------------
__global__ void __launch_bounds__(TPB, 3)
fused_maskhead_kernel(const float* __restrict__ feats,     // [N, 8, H, W]
                      const float* __restrict__ params,    // [n_inst, 169]
                      const float* __restrict__ ilocs,     // [n_inst, 2]
                      const int*   __restrict__ iminds,    // [n_inst]
                      const int*   __restrict__ levels,    // [n_inst]
                      float*       __restrict__ out)       // [n_inst,1,OH,OW]
{
    const int inst = blockIdx.y;
    const int R0   = blockIdx.x * ROWS_OUT;
    const int tid  = threadIdx.x;

    __shared__ u64   sw[NPARAMS];               // duplicated {w,w} packed weights
    __shared__ float tile[(ROWS_OUT + 1) * WW]; // logits tile incl. halo row

    for (int i = tid; i < NPARAMS; i += TPB) {
        float v = params[inst * NPARAMS + i];
        sw[i] = pk2(v, v);
    }

    const float Lx = ilocs[2 * inst];
    const float Ly = ilocs[2 * inst + 1];
    const float inv_soi = 1.0f / (float)(64 << levels[inst]);  // SOI = 2^k -> exact
    const float* fb = feats + (size_t)iminds[inst] * (NCH * HWP);

    __syncthreads();

    // -------- phase 1: compute logits rows [r_begin, r_end) into tile --------
    const int r_begin = (R0 > 0) ? R0 - 1 : 0;
    const int r_end   = (R0 + ROWS_OUT < HH) ? R0 + ROWS_OUT : HH;
    const int npairs  = (r_end - r_begin) * NPAIR;   // <= 988

    for (int i = tid; i < npairs; i += TPB) {
        const int rr  = i / NPAIR;
        const int jj  = i - rr * NPAIR;
        const int row = r_begin + rr;
        const int p   = row * WW + 2 * jj;

        // one rounding in subtract, exact scale by 2^-k: bit-identical to ref divide
        const float rx0 = (Lx - (float)(16 * jj + 4))  * inv_soi;
        const float rx1 = (Lx - (float)(16 * jj + 12)) * inv_soi;
        const float ry  = (Ly - (float)(row * 8 + 4))  * inv_soi;
        const u64 inx = pk2(rx0, rx1);
        const u64 iny = pk2(ry, ry);

        // ---- layer 0: 10 -> 8 ----
        u64 a0[8];
#pragma unroll
        for (int c = 0; c < 8; c++) {
            u64 acc = sw[152 + c];
            acc = ffma2(sw[c * 10 + 0], inx, acc);
            acc = ffma2(sw[c * 10 + 1], iny, acc);
            a0[c] = acc;
        }
#pragma unroll
        for (int cc = 0; cc < 8; cc++) {
            const u64 in = *(const u64*)(fb + cc * HWP + p);
#pragma unroll
            for (int c = 0; c < 8; c++)
                a0[c] = ffma2(sw[c * 10 + 2 + cc], in, a0[c]);
        }

        // ---- layer 1: relu -> 8 -> 8 ----
        u64 a1[8];
#pragma unroll
        for (int c = 0; c < 8; c++) a1[c] = sw[160 + c];
#pragma unroll
        for (int k = 0; k < 8; k++) {
            const u64 r = relu2(a0[k]);
#pragma unroll
            for (int c = 0; c < 8; c++)
                a1[c] = ffma2(sw[80 + c * 8 + k], r, a1[c]);
        }

        // ---- layer 2: relu -> 8 -> 1 ----
        u64 a2 = sw[168];
#pragma unroll
        for (int k = 0; k < 8; k++)
            a2 = ffma2(sw[144 + k], relu2(a1[k]), a2);

        *(u64*)&tile[rr * WW + 2 * jj] = a2;
    }

    __syncthreads();

    // -------- phase 2: x2 aligned_bilinear stencil from smem, float4 stores --------
    // Each position (r, colpair j) emits output cols [4j, 4j+4) of rows 2r, 2r+1.
    const int nro  = ((R0 + ROWS_OUT < HH) ? ROWS_OUT : HH - R0);
    const int npos = nro * NPAIR;
    float* ob_base = out + (size_t)inst * (OH * OW);

    for (int i = tid; i < npos; i += TPB) {
        const int rr  = i / NPAIR;
        const int j   = i - rr * NPAIR;
        const int r   = R0 + rr;
        const int tr  = r - r_begin;
        const int trm = ((r > 0) ? r - 1 : 0) - r_begin;
        const int qm  = (j > 0) ? (2 * j - 1) : 0;

        float A1, A2, C1, C2;
        upk2(A1, A2, *(const u64*)&tile[trm * WW + 2 * j]);
        upk2(C1, C2, *(const u64*)&tile[tr  * WW + 2 * j]);
        const float A0 = tile[trm * WW + qm];
        const float C0 = tile[tr  * WW + qm];

        float4 top, bot;
        top.x = 0.5f * (0.5f * (A0 + A1) + 0.5f * (C0 + C1));
        top.y = 0.5f * (A1 + C1);
        top.z = 0.5f * (0.5f * (A1 + A2) + 0.5f * (C1 + C2));
        top.w = 0.5f * (A2 + C2);
        bot.x = 0.5f * (C0 + C1);
        bot.y = C1;
        bot.z = 0.5f * (C1 + C2);
        bot.w = C2;

        float* ob = ob_base + (2 * r) * OW + 4 * j;
        *(float4*)ob        = top;
        *(float4*)(ob + OW) = bot;
    }
}

// ---------------------------------------------------------------------------
extern "C" void kernel_launch(void* const* d_in, const int* in_sizes, int n_in,
                              void* d_out, int out_size)
{
    const float* feats  = (const float*)d_in[0];
    const float* params = (const float*)d_in[1];
    const float* ilocs  = (const float*)d_in[2];
    const int*   iminds = (const int*)d_in[3];
    const int*   levels = (const int*)d_in[4];

    int n_inst = in_sizes[1] / NPARAMS;     // 400
    if (n_inst > MAXINST) n_inst = MAXINST;

    dim3 g((HH + ROWS_OUT - 1) / ROWS_OUT, n_inst);   // (9, 400)
    fused_maskhead_kernel<<<g, TPB>>>(feats, params, ilocs, iminds, levels,
                                      (float*)d_out);
}

// round 10
// speedup vs baseline: 7.9624x; 7.9624x over previous
#include <cuda_runtime.h>

// Fixed shapes from setup_inputs
#define HH 100
#define WW 152
#define NPAIR 76           // WW/2
#define TOTPAIR 7600       // HH*NPAIR
#define HWP 15200          // HH*WW
#define NCH 8
#define NPARAMS 169
#define MAXINST 400
#define OH 200
#define OW 304
#define TPB 256

// Scratch for logits (static __device__ allocation — allowed)
__device__ float g_logits[MAXINST * HWP];

typedef unsigned long long u64;

__device__ __forceinline__ u64 pk2(float a, float b) {
    u64 r;
    asm("mov.b64 %0, {%1,%2};" : "=l"(r) : "r"(__float_as_uint(a)), "r"(__float_as_uint(b)));
    return r;
}
__device__ __forceinline__ void upk2(float& a, float& b, u64 x) {
    unsigned int lo, hi;
    asm("mov.b64 {%0,%1}, %2;" : "=r"(lo), "=r"(hi) : "l"(x));
    a = __uint_as_float(lo); b = __uint_as_float(hi);
}
__device__ __forceinline__ u64 ffma2(u64 a, u64 b, u64 c) {
    u64 d;
    asm("fma.rn.f32x2 %0, %1, %2, %3;" : "=l"(d) : "l"(a), "l"(b), "l"(c));
    return d;
}
__device__ __forceinline__ u64 relu2(u64 x) {
    float a, b; upk2(a, b, x);
    a = fmaxf(a, 0.0f); b = fmaxf(b, 0.0f);
    return pk2(a, b);
}

// ---------------------------------------------------------------------------
// Kernel A: per-instance 3-layer 1x1-conv MLP -> logits [n_inst, HW].
// ONE pixel-pair per thread (no loop): live set ~60 regs, 3 blocks/SM pinned.
// grid (30, n_inst), block 256.
// ---------------------------------------------------------------------------
__global__ void __launch_bounds__(TPB, 3)
logits_kernel(const float* __restrict__ feats,     // [N, 8, H, W]
              const float* __restrict__ params,    // [n_inst, 169]
              const float* __restrict__ ilocs,     // [n_inst, 2]
              const int*   __restrict__ iminds,    // [n_inst]
              const int*   __restrict__ levels)    // [n_inst]
{
    const int inst = blockIdx.y;
    const int tid  = threadIdx.x;

    __shared__ u64 sw[NPARAMS];   // duplicated {w,w} packed weights

    for (int i = tid; i < NPARAMS; i += TPB) {
        float v = params[inst * NPARAMS + i];
        sw[i] = pk2(v, v);
    }

    const float Lx = ilocs[2 * inst];
    const float Ly = ilocs[2 * inst + 1];
    const float inv_soi = 1.0f / (float)(64 << levels[inst]);  // SOI = 2^k -> exact
    const float* fb = feats + (size_t)iminds[inst] * (NCH * HWP);

    __syncthreads();

    const int i = blockIdx.x * TPB + tid;
    if (i >= TOTPAIR) return;

    const int row = i / NPAIR;
    const int jj  = i - row * NPAIR;
    const int p   = row * WW + 2 * jj;

    // one rounding in subtract, exact scale by 2^-k: bit-identical to ref divide
    const float rx0 = (Lx - (float)(16 * jj + 4))  * inv_soi;
    const float rx1 = (Lx - (float)(16 * jj + 12)) * inv_soi;
    const float ry  = (Ly - (float)(row * 8 + 4))  * inv_soi;
    const u64 inx = pk2(rx0, rx1);
    const u64 iny = pk2(ry, ry);

    // ---- layer 0: 10 -> 8 ----
    u64 a0[8];
#pragma unroll
    for (int c = 0; c < 8; c++) {
        u64 acc = sw[152 + c];
        acc = ffma2(sw[c * 10 + 0], inx, acc);
        acc = ffma2(sw[c * 10 + 1], iny, acc);
        a0[c] = acc;
    }
#pragma unroll
    for (int cc = 0; cc < 8; cc++) {
        const u64 in = *(const u64*)(fb + cc * HWP + p);
#pragma unroll
        for (int c = 0; c < 8; c++)
            a0[c] = ffma2(sw[c * 10 + 2 + cc], in, a0[c]);
    }

    // ---- layer 1: relu -> 8 -> 8 ----
    u64 a1[8];
#pragma unroll
    for (int c = 0; c < 8; c++) a1[c] = sw[160 + c];
#pragma unroll
    for (int k = 0; k < 8; k++) {
        const u64 r = relu2(a0[k]);
#pragma unroll
        for (int c = 0; c < 8; c++)
            a1[c] = ffma2(sw[80 + c * 8 + k], r, a1[c]);
    }

    // ---- layer 2: relu -> 8 -> 1 ----
    u64 a2 = sw[168];
#pragma unroll
    for (int k = 0; k < 8; k++)
        a2 = ffma2(sw[144 + k], relu2(a1[k]), a2);

    *(u64*)(g_logits + (size_t)inst * HWP + p) = a2;
}

// ---------------------------------------------------------------------------
// Kernel B: aligned_bilinear x2 upsample, one 2x4 output block per thread.
// Position (r, colpair j) emits output cols [4j, 4j+4) of rows 2r, 2r+1.
// Scratch (24 MB) is L2-resident -> reads are cheap; writes are float4.
// ---------------------------------------------------------------------------
__global__ void __launch_bounds__(TPB)
upsample_kernel(float* __restrict__ out)
{
    const int inst = blockIdx.y;
    const int i    = blockIdx.x * TPB + threadIdx.x;
    if (i >= TOTPAIR) return;

    const int r  = i / NPAIR;
    const int j  = i - r * NPAIR;
    const int rm = (r > 0) ? r - 1 : 0;
    const int qm = (j > 0) ? (2 * j - 1) : 0;

    const float* T = g_logits + (size_t)inst * HWP;

    float A1, A2, C1, C2;
    upk2(A1, A2, *(const u64*)(T + rm * WW + 2 * j));
    upk2(C1, C2, *(const u64*)(T + r  * WW + 2 * j));
    const float A0 = T[rm * WW + qm];
    const float C0 = T[r  * WW + qm];

    float4 top, bot;
    top.x = 0.5f * (0.5f * (A0 + A1) + 0.5f * (C0 + C1));
    top.y = 0.5f * (A1 + C1);
    top.z = 0.5f * (0.5f * (A1 + A2) + 0.5f * (C1 + C2));
    top.w = 0.5f * (A2 + C2);
    bot.x = 0.5f * (C0 + C1);
    bot.y = C1;
    bot.z = 0.5f * (C1 + C2);
    bot.w = C2;

    float* ob = out + (size_t)inst * (OH * OW) + (2 * r) * OW + 4 * j;
    *(float4*)ob        = top;
    *(float4*)(ob + OW) = bot;
}

// ---------------------------------------------------------------------------
extern "C" void kernel_launch(void* const* d_in, const int* in_sizes, int n_in,
                              void* d_out, int out_size)
{
    const float* feats  = (const float*)d_in[0];
    const float* params = (const float*)d_in[1];
    const float* ilocs  = (const float*)d_in[2];
    const int*   iminds = (const int*)d_in[3];
    const int*   levels = (const int*)d_in[4];

    int n_inst = in_sizes[1] / NPARAMS;     // 400
    if (n_inst > MAXINST) n_inst = MAXINST;

    dim3 ga((TOTPAIR + TPB - 1) / TPB, n_inst);   // (30, 400)
    logits_kernel<<<ga, TPB>>>(feats, params, ilocs, iminds, levels);

    dim3 gb((TOTPAIR + TPB - 1) / TPB, n_inst);   // (30, 400)
    upsample_kernel<<<gb, TPB>>>((float*)d_out);
}

// round 12
// speedup vs baseline: 9.3113x; 1.1694x over previous
#include <cuda_runtime.h>

// Fixed shapes from setup_inputs
#define HH 100
#define WW 152
#define NPAIR 76           // WW/2
#define TOTPAIR 7600       // HH*NPAIR
#define HWP 15200          // HH*WW
#define NCH 8
#define NPARAMS 169
#define MAXINST 400
#define OH 200
#define OW 304
#define TPB 256

// Scratch for logits (static __device__ allocation — allowed)
__device__ float g_logits[MAXINST * HWP];

typedef unsigned long long u64;

__device__ __forceinline__ u64 pk2(float a, float b) {
    u64 r;
    asm("mov.b64 %0, {%1,%2};" : "=l"(r) : "r"(__float_as_uint(a)), "r"(__float_as_uint(b)));
    return r;
}
__device__ __forceinline__ void upk2(float& a, float& b, u64 x) {
    unsigned int lo, hi;
    asm("mov.b64 {%0,%1}, %2;" : "=r"(lo), "=r"(hi) : "l"(x));
    a = __uint_as_float(lo); b = __uint_as_float(hi);
}
__device__ __forceinline__ u64 ffma2(u64 a, u64 b, u64 c) {
    u64 d;
    asm("fma.rn.f32x2 %0, %1, %2, %3;" : "=l"(d) : "l"(a), "l"(b), "l"(c));
    return d;
}
__device__ __forceinline__ u64 relu2(u64 x) {
    float a, b; upk2(a, b, x);
    a = fmaxf(a, 0.0f); b = fmaxf(b, 0.0f);
    return pk2(a, b);
}

// ---------------------------------------------------------------------------
// Kernel A: per-instance 3-layer 1x1-conv MLP -> logits [n_inst, HW].
// TWO pixel-pairs per thread, processed together through the layers so each
// weight LDS feeds 2 FFMA2s (fma-pipe-bound: 338 LDS-cyc < 608 fma-cyc/warp).
// launch_bounds(256,2): 128-reg budget for the ~100-reg live set, no spills.
// grid (15, n_inst): block covers 512 consecutive pairs as (tid, tid+256).
// ---------------------------------------------------------------------------
__global__ void __launch_bounds__(TPB, 2)
logits_kernel(const float* __restrict__ feats,     // [N, 8, H, W]
              const float* __restrict__ params,    // [n_inst, 169]
              const float* __restrict__ ilocs,     // [n_inst, 2]
              const int*   __restrict__ iminds,    // [n_inst]
              const int*   __restrict__ levels)    // [n_inst]
{
    const int inst = blockIdx.y;
    const int tid  = threadIdx.x;

    __shared__ u64 sw[NPARAMS];   // duplicated {w,w} packed weights

    for (int i = tid; i < NPARAMS; i += TPB) {
        float v = params[inst * NPARAMS + i];
        sw[i] = pk2(v, v);
    }

    const float Lx = ilocs[2 * inst];
    const float Ly = ilocs[2 * inst + 1];
    const float inv_soi = 1.0f / (float)(64 << levels[inst]);  // SOI = 2^k -> exact
    const float* fb = feats + (size_t)iminds[inst] * (NCH * HWP);

    __syncthreads();

    const int base = blockIdx.x * (2 * TPB) + tid;
    const int i0   = base;                 // always < TOTPAIR (grid sized exactly)
    int  i1        = base + TPB;
    const bool v1  = (i1 < TOTPAIR);
    if (!v1) i1 = i0;                      // duplicate keeps loads in-bounds

    int p[2];
    u64 inx[2], iny[2];
    {
        const int idx[2] = {i0, i1};
#pragma unroll
        for (int q = 0; q < 2; q++) {
            const int row = idx[q] / NPAIR;
            const int jj  = idx[q] - row * NPAIR;
            p[q] = row * WW + 2 * jj;
            // one rounding in subtract, exact scale by 2^-k: bit-identical to ref
            const float rx0 = (Lx - (float)(16 * jj + 4))  * inv_soi;
            const float rx1 = (Lx - (float)(16 * jj + 12)) * inv_soi;
            const float ry  = (Ly - (float)(row * 8 + 4))  * inv_soi;
            inx[q] = pk2(rx0, rx1);
            iny[q] = pk2(ry, ry);
        }
    }

    // ---- layer 0: 10 -> 8 ----
    u64 a0[8][2];
#pragma unroll
    for (int c = 0; c < 8; c++) {
        const u64 b  = sw[152 + c];
        const u64 w0 = sw[c * 10 + 0];
        const u64 w1 = sw[c * 10 + 1];
#pragma unroll
        for (int q = 0; q < 2; q++)
            a0[c][q] = ffma2(w1, iny[q], ffma2(w0, inx[q], b));
    }
#pragma unroll
    for (int cc = 0; cc < 8; cc++) {
        u64 in[2];
        in[0] = *(const u64*)(fb + cc * HWP + p[0]);
        in[1] = *(const u64*)(fb + cc * HWP + p[1]);
#pragma unroll
        for (int c = 0; c < 8; c++) {
            const u64 w = sw[c * 10 + 2 + cc];
            a0[c][0] = ffma2(w, in[0], a0[c][0]);
            a0[c][1] = ffma2(w, in[1], a0[c][1]);
        }
    }

    // ---- layer 1: relu -> 8 -> 8 ----
    u64 a1[8][2];
#pragma unroll
    for (int c = 0; c < 8; c++) {
        const u64 b = sw[160 + c];
        a1[c][0] = b; a1[c][1] = b;
    }
#pragma unroll
    for (int k = 0; k < 8; k++) {
        const u64 r0 = relu2(a0[k][0]);
        const u64 r1 = relu2(a0[k][1]);
#pragma unroll
        for (int c = 0; c < 8; c++) {
            const u64 w = sw[80 + c * 8 + k];
            a1[c][0] = ffma2(w, r0, a1[c][0]);
            a1[c][1] = ffma2(w, r1, a1[c][1]);
        }
    }

    // ---- layer 2: relu -> 8 -> 1 ----
    u64 a2[2];
    a2[0] = sw[168]; a2[1] = sw[168];
#pragma unroll
    for (int k = 0; k < 8; k++) {
        const u64 w = sw[144 + k];
        a2[0] = ffma2(w, relu2(a1[k][0]), a2[0]);
        a2[1] = ffma2(w, relu2(a1[k][1]), a2[1]);
    }

    float* outp = g_logits + (size_t)inst * HWP;
    *(u64*)(outp + p[0]) = a2[0];
    if (v1) *(u64*)(outp + p[1]) = a2[1];
}

// ---------------------------------------------------------------------------
// Kernel B: aligned_bilinear x2 upsample, one 2x4 output block per thread.
// (unchanged from round 10: measured 20.2 us)
// ---------------------------------------------------------------------------
__global__ void __launch_bounds__(TPB)
upsample_kernel(float* __restrict__ out)
{
    const int inst = blockIdx.y;
    const int i    = blockIdx.x * TPB + threadIdx.x;
    if (i >= TOTPAIR) return;

    const int r  = i / NPAIR;
    const int j  = i - r * NPAIR;
    const int rm = (r > 0) ? r - 1 : 0;
    const int qm = (j > 0) ? (2 * j - 1) : 0;

    const float* T = g_logits + (size_t)inst * HWP;

    float A1, A2, C1, C2;
    upk2(A1, A2, *(const u64*)(T + rm * WW + 2 * j));
    upk2(C1, C2, *(const u64*)(T + r  * WW + 2 * j));
    const float A0 = T[rm * WW + qm];
    const float C0 = T[r  * WW + qm];

    float4 top, bot;
    top.x = 0.5f * (0.5f * (A0 + A1) + 0.5f * (C0 + C1));
    top.y = 0.5f * (A1 + C1);
    top.z = 0.5f * (0.5f * (A1 + A2) + 0.5f * (C1 + C2));
    top.w = 0.5f * (A2 + C2);
    bot.x = 0.5f * (C0 + C1);
    bot.y = C1;
    bot.z = 0.5f * (C1 + C2);
    bot.w = C2;

    float* ob = out + (size_t)inst * (OH * OW) + (2 * r) * OW + 4 * j;
    *(float4*)ob        = top;
    *(float4*)(ob + OW) = bot;
}

// ---------------------------------------------------------------------------
extern "C" void kernel_launch(void* const* d_in, const int* in_sizes, int n_in,
                              void* d_out, int out_size)
{
    const float* feats  = (const float*)d_in[0];
    const float* params = (const float*)d_in[1];
    const float* ilocs  = (const float*)d_in[2];
    const int*   iminds = (const int*)d_in[3];
    const int*   levels = (const int*)d_in[4];

    int n_inst = in_sizes[1] / NPARAMS;     // 400
    if (n_inst > MAXINST) n_inst = MAXINST;

    dim3 ga((TOTPAIR + 2 * TPB - 1) / (2 * TPB), n_inst);   // (15, 400)
    logits_kernel<<<ga, TPB>>>(feats, params, ilocs, iminds, levels);

    dim3 gb((TOTPAIR + TPB - 1) / TPB, n_inst);             // (30, 400)
    upsample_kernel<<<gb, TPB>>>((float*)d_out);
}

// round 13
// speedup vs baseline: 9.5508x; 1.0257x over previous
#include <cuda_runtime.h>

// Fixed shapes from setup_inputs
#define HH 100
#define WW 152
#define NPAIR 76           // WW/2
#define TOTPAIR 7600       // HH*NPAIR
#define NGRP 38            // NPAIR/2 (two col-pairs per upsample thread)
#define TOTGRP 3800        // HH*NGRP
#define HWP 15200          // HH*WW
#define NCH 8
#define NPARAMS 169
#define MAXINST 400
#define OH 200
#define OW 304

// Scratch for logits (static __device__ allocation — allowed)
__device__ float g_logits[MAXINST * HWP];

typedef unsigned long long u64;

__device__ __forceinline__ u64 pk2(float a, float b) {
    u64 r;
    asm("mov.b64 %0, {%1,%2};" : "=l"(r) : "r"(__float_as_uint(a)), "r"(__float_as_uint(b)));
    return r;
}
__device__ __forceinline__ void upk2(float& a, float& b, u64 x) {
    unsigned int lo, hi;
    asm("mov.b64 {%0,%1}, %2;" : "=r"(lo), "=r"(hi) : "l"(x));
    a = __uint_as_float(lo); b = __uint_as_float(hi);
}
__device__ __forceinline__ u64 ffma2(u64 a, u64 b, u64 c) {
    u64 d;
    asm("fma.rn.f32x2 %0, %1, %2, %3;" : "=l"(d) : "l"(a), "l"(b), "l"(c));
    return d;
}
__device__ __forceinline__ u64 relu2(u64 x) {
    float a, b; upk2(a, b, x);
    a = fmaxf(a, 0.0f); b = fmaxf(b, 0.0f);
    return pk2(a, b);
}

// ---------------------------------------------------------------------------
// Kernel A: per-instance 3-layer 1x1-conv MLP -> logits [n_inst, HW].
// FOUR pixel-pairs per thread (measured-best LDS amortization: 42 LDS/pair),
// with launch_bounds(128,3) pinning 12 warps/SM (round 3 ran only 8).
// Peak live set ~150 regs (a0[32]+a1[32] u64 at the layer transition) within
// the 170-reg budget. grid (15, n_inst), block 128.
// ---------------------------------------------------------------------------
__global__ void __launch_bounds__(128, 3)
logits_kernel(const float* __restrict__ feats,     // [N, 8, H, W]
              const float* __restrict__ params,    // [n_inst, 169]
              const float* __restrict__ ilocs,     // [n_inst, 2]
              const int*   __restrict__ iminds,    // [n_inst]
              const int*   __restrict__ levels)    // [n_inst]
{
    const int inst = blockIdx.y;
    const int tid  = threadIdx.x;

    __shared__ u64 sw[NPARAMS];   // duplicated {w,w} packed weights

    for (int i = tid; i < NPARAMS; i += 128) {
        float v = params[inst * NPARAMS + i];
        sw[i] = pk2(v, v);
    }

    const float Lx = ilocs[2 * inst];
    const float Ly = ilocs[2 * inst + 1];
    const float inv_soi = 1.0f / (float)(64 << levels[inst]);  // SOI = 2^k -> exact
    const float* fb = feats + (size_t)iminds[inst] * (NCH * HWP);

    __syncthreads();

    const int base = blockIdx.x * 512 + tid;   // base < TOTPAIR for grid.x=15

    int  p[4];
    bool v[4];
    u64  inx[4], iny[4];
#pragma unroll
    for (int q = 0; q < 4; q++) {
        int i = base + q * 128;
        v[q] = (i < TOTPAIR);
        if (!v[q]) i = base;                   // duplicate keeps loads in-bounds
        const int row = i / NPAIR;
        const int jj  = i - row * NPAIR;
        p[q] = row * WW + 2 * jj;
        // one rounding in subtract, exact scale by 2^-k: bit-identical to ref
        const float rx0 = (Lx - (float)(16 * jj + 4))  * inv_soi;
        const float rx1 = (Lx - (float)(16 * jj + 12)) * inv_soi;
        const float ry  = (Ly - (float)(row * 8 + 4))  * inv_soi;
        inx[q] = pk2(rx0, rx1);
        iny[q] = pk2(ry, ry);
    }

    // ---- layer 0: 10 -> 8 ----
    u64 a0[8][4];
#pragma unroll
    for (int c = 0; c < 8; c++) {
        const u64 b  = sw[152 + c];
        const u64 w0 = sw[c * 10 + 0];
        const u64 w1 = sw[c * 10 + 1];
#pragma unroll
        for (int q = 0; q < 4; q++)
            a0[c][q] = ffma2(w1, iny[q], ffma2(w0, inx[q], b));
    }
#pragma unroll
    for (int cc = 0; cc < 8; cc++) {
        u64 in[4];
#pragma unroll
        for (int q = 0; q < 4; q++)
            in[q] = *(const u64*)(fb + cc * HWP + p[q]);
#pragma unroll
        for (int c = 0; c < 8; c++) {
            const u64 w = sw[c * 10 + 2 + cc];
#pragma unroll
            for (int q = 0; q < 4; q++)
                a0[c][q] = ffma2(w, in[q], a0[c][q]);
        }
    }

    // ---- layer 1: relu -> 8 -> 8 (a0[k] dies as k advances) ----
    u64 a1[8][4];
#pragma unroll
    for (int c = 0; c < 8; c++) {
        const u64 b = sw[160 + c];
#pragma unroll
        for (int q = 0; q < 4; q++) a1[c][q] = b;
    }
#pragma unroll
    for (int k = 0; k < 8; k++) {
        u64 r[4];
#pragma unroll
        for (int q = 0; q < 4; q++) r[q] = relu2(a0[k][q]);
#pragma unroll
        for (int c = 0; c < 8; c++) {
            const u64 w = sw[80 + c * 8 + k];
#pragma unroll
            for (int q = 0; q < 4; q++)
                a1[c][q] = ffma2(w, r[q], a1[c][q]);
        }
    }

    // ---- layer 2: relu -> 8 -> 1 ----
    u64 a2[4];
    {
        const u64 b2 = sw[168];
#pragma unroll
        for (int q = 0; q < 4; q++) a2[q] = b2;
    }
#pragma unroll
    for (int k = 0; k < 8; k++) {
        const u64 w = sw[144 + k];
#pragma unroll
        for (int q = 0; q < 4; q++)
            a2[q] = ffma2(w, relu2(a1[k][q]), a2[q]);
    }

    float* outp = g_logits + (size_t)inst * HWP;
#pragma unroll
    for (int q = 0; q < 4; q++)
        if (v[q]) *(u64*)(outp + p[q]) = a2[q];
}

// ---------------------------------------------------------------------------
// Kernel B: aligned_bilinear x2 upsample, TWO adjacent 2x4 blocks per thread
// (one 2x8 output block, cols 8g..8g+7 of rows 2r, 2r+1). The shared boundary
// logit is loaded once; FP association identical to the verified stencil.
// ---------------------------------------------------------------------------
__global__ void __launch_bounds__(256)
upsample_kernel(float* __restrict__ out)
{
    const int inst = blockIdx.y;
    const int i    = blockIdx.x * 256 + threadIdx.x;
    if (i >= TOTGRP) return;

    const int r   = i / NGRP;
    const int g   = i - r * NGRP;
    const int col = 4 * g;                    // logit cols col..col+3
    const int rm  = (r > 0) ? r - 1 : 0;
    const int qm  = (g > 0) ? col - 1 : 0;

    const float* T  = g_logits + (size_t)inst * HWP;
    const float* Ta = T + rm * WW;
    const float* Tc = T + r  * WW;

    float a0, a1, b0, b1, c0, c1, d0, d1;
    upk2(a0, a1, *(const u64*)(Ta + col));
    upk2(b0, b1, *(const u64*)(Ta + col + 2));
    upk2(c0, c1, *(const u64*)(Tc + col));
    upk2(d0, d1, *(const u64*)(Tc + col + 2));
    const float A0 = Ta[qm];
    const float C0 = Tc[qm];

    // position 1: A0,a0,a1 / C0,c0,c1   -> out cols 8g..8g+3
    float4 t1, o1;
    t1.x = 0.5f * (0.5f * (A0 + a0) + 0.5f * (C0 + c0));
    t1.y = 0.5f * (a0 + c0);
    t1.z = 0.5f * (0.5f * (a0 + a1) + 0.5f * (c0 + c1));
    t1.w = 0.5f * (a1 + c1);
    o1.x = 0.5f * (C0 + c0);
    o1.y = c0;
    o1.z = 0.5f * (c0 + c1);
    o1.w = c1;

    // position 2: a1,b0,b1 / c1,d0,d1   -> out cols 8g+4..8g+7
    float4 t2, o2;
    t2.x = 0.5f * (0.5f * (a1 + b0) + 0.5f * (c1 + d0));
    t2.y = 0.5f * (b0 + d0);
    t2.z = 0.5f * (0.5f * (b0 + b1) + 0.5f * (d0 + d1));
    t2.w = 0.5f * (b1 + d1);
    o2.x = 0.5f * (c1 + d0);
    o2.y = d0;
    o2.z = 0.5f * (d0 + d1);
    o2.w = d1;

    float* ob = out + (size_t)inst * (OH * OW) + (2 * r) * OW + 8 * g;
    *(float4*)(ob)          = t1;
    *(float4*)(ob + 4)      = t2;
    *(float4*)(ob + OW)     = o1;
    *(float4*)(ob + OW + 4) = o2;
}

// ---------------------------------------------------------------------------
extern "C" void kernel_launch(void* const* d_in, const int* in_sizes, int n_in,
                              void* d_out, int out_size)
{
    const float* feats  = (const float*)d_in[0];
    const float* params = (const float*)d_in[1];
    const float* ilocs  = (const float*)d_in[2];
    const int*   iminds = (const int*)d_in[3];
    const int*   levels = (const int*)d_in[4];

    int n_inst = in_sizes[1] / NPARAMS;     // 400
    if (n_inst > MAXINST) n_inst = MAXINST;

    dim3 ga((TOTPAIR + 511) / 512, n_inst);   // (15, 400), 128 threads
    logits_kernel<<<ga, 128>>>(feats, params, ilocs, iminds, levels);

    dim3 gb((TOTGRP + 255) / 256, n_inst);    // (15, 400), 256 threads
    upsample_kernel<<<gb, 256>>>((float*)d_out);
}

// round 14
// speedup vs baseline: 10.7221x; 1.1226x over previous
#include <cuda_runtime.h>

// Fixed shapes from setup_inputs
#define HH 100
#define WW 152
#define NPAIR 76           // WW/2
#define TOTPAIR 7600       // HH*NPAIR
#define HWP 15200          // HH*WW
#define NCH 8
#define NPARAMS 169
#define MAXINST 400
#define OH 200
#define OW 304

// Scratch for logits (static __device__ allocation — allowed)
__device__ float g_logits[MAXINST * HWP];

typedef unsigned long long u64;

__device__ __forceinline__ u64 pk2(float a, float b) {
    u64 r;
    asm("mov.b64 %0, {%1,%2};" : "=l"(r) : "r"(__float_as_uint(a)), "r"(__float_as_uint(b)));
    return r;
}
__device__ __forceinline__ void upk2(float& a, float& b, u64 x) {
    unsigned int lo, hi;
    asm("mov.b64 {%0,%1}, %2;" : "=r"(lo), "=r"(hi) : "l"(x));
    a = __uint_as_float(lo); b = __uint_as_float(hi);
}
__device__ __forceinline__ u64 ffma2(u64 a, u64 b, u64 c) {
    u64 d;
    asm("fma.rn.f32x2 %0, %1, %2, %3;" : "=l"(d) : "l"(a), "l"(b), "l"(c));
    return d;
}
__device__ __forceinline__ u64 relu2(u64 x) {
    float a, b; upk2(a, b, x);
    a = fmaxf(a, 0.0f); b = fmaxf(b, 0.0f);
    return pk2(a, b);
}

// ---------------------------------------------------------------------------
// Kernel A: per-instance 3-layer 1x1-conv MLP -> logits [n_inst, HW].
// FOUR pixel-pairs per thread. Weights stored TRANSPOSED in shared so every
// inner loop reads two consecutive u64 weights with one LDS.128 (ulonglong2):
// ~86 LDS per 4 pairs instead of 169. Math order identical to prior rounds.
// ---------------------------------------------------------------------------
__global__ void __launch_bounds__(128, 3)
logits_kernel(const float* __restrict__ feats,     // [N, 8, H, W]
              const float* __restrict__ params,    // [n_inst, 169]
              const float* __restrict__ ilocs,     // [n_inst, 2]
              const int*   __restrict__ iminds,    // [n_inst]
              const int*   __restrict__ levels)    // [n_inst]
{
    const int inst = blockIdx.y;
    const int tid  = threadIdx.x;

    // Transposed, duplicated {w,w} packed weights (all 16B-aligned rows)
    __shared__ alignas(16) u64 swc[16];      // (w0[c], w1[c]) interleaved
    __shared__ alignas(16) u64 sw0t[8][8];   // [cc][c]  layer-0 feat weights
    __shared__ alignas(16) u64 sw1t[8][8];   // [k][c]   layer-1 weights
    __shared__ alignas(16) u64 sw2[8];       // layer-2 weights
    __shared__ alignas(16) u64 sb0[8];
    __shared__ alignas(16) u64 sb1[8];
    __shared__ u64 sb2;

    for (int i = tid; i < NPARAMS; i += 128) {
        const float vv = params[inst * NPARAMS + i];
        const u64 w = pk2(vv, vv);
        if (i < 80) {                       // w0: [c][j], j<10
            const int c = i / 10, j = i - c * 10;
            if (j < 2) swc[2 * c + j] = w;
            else       sw0t[j - 2][c] = w;
        } else if (i < 144) {               // w1: [c][k]
            const int idx = i - 80;
            const int c = idx / 8, k = idx - c * 8;
            sw1t[k][c] = w;
        } else if (i < 152) sw2[i - 144] = w;
        else if (i < 160)   sb0[i - 152] = w;
        else if (i < 168)   sb1[i - 160] = w;
        else                sb2 = w;
    }

    const float Lx = ilocs[2 * inst];
    const float Ly = ilocs[2 * inst + 1];
    const float inv_soi = 1.0f / (float)(64 << levels[inst]);  // SOI = 2^k -> exact
    const float* fb = feats + (size_t)iminds[inst] * (NCH * HWP);

    __syncthreads();

    const int base = blockIdx.x * 512 + tid;   // base < TOTPAIR for grid.x=15

    int  p[4];
    bool v[4];
    u64  inx[4], iny[4];
#pragma unroll
    for (int q = 0; q < 4; q++) {
        int i = base + q * 128;
        v[q] = (i < TOTPAIR);
        if (!v[q]) i = base;                   // duplicate keeps loads in-bounds
        const int row = i / NPAIR;
        const int jj  = i - row * NPAIR;
        p[q] = row * WW + 2 * jj;
        // one rounding in subtract, exact scale by 2^-k: bit-identical to ref
        const float rx0 = (Lx - (float)(16 * jj + 4))  * inv_soi;
        const float rx1 = (Lx - (float)(16 * jj + 12)) * inv_soi;
        const float ry  = (Ly - (float)(row * 8 + 4))  * inv_soi;
        inx[q] = pk2(rx0, rx1);
        iny[q] = pk2(ry, ry);
    }

    // ---- layer 0: 10 -> 8 ----
    u64 a0[8][4];
#pragma unroll
    for (int c = 0; c < 8; c += 2) {
        const ulonglong2 bb  = *(const ulonglong2*)&sb0[c];
        const ulonglong2 wcA = *(const ulonglong2*)&swc[2 * c];      // w0,w1 of c
        const ulonglong2 wcB = *(const ulonglong2*)&swc[2 * c + 2];  // w0,w1 of c+1
#pragma unroll
        for (int q = 0; q < 4; q++) {
            a0[c][q]     = ffma2(wcA.y, iny[q], ffma2(wcA.x, inx[q], bb.x));
            a0[c + 1][q] = ffma2(wcB.y, iny[q], ffma2(wcB.x, inx[q], bb.y));
        }
    }
#pragma unroll
    for (int cc = 0; cc < 8; cc++) {
        u64 in[4];
#pragma unroll
        for (int q = 0; q < 4; q++)
            in[q] = *(const u64*)(fb + cc * HWP + p[q]);
#pragma unroll
        for (int c = 0; c < 8; c += 2) {
            const ulonglong2 ww = *(const ulonglong2*)&sw0t[cc][c];
#pragma unroll
            for (int q = 0; q < 4; q++) {
                a0[c][q]     = ffma2(ww.x, in[q], a0[c][q]);
                a0[c + 1][q] = ffma2(ww.y, in[q], a0[c + 1][q]);
            }
        }
    }

    // ---- layer 1: relu -> 8 -> 8 ----
    u64 a1[8][4];
#pragma unroll
    for (int c = 0; c < 8; c += 2) {
        const ulonglong2 bb = *(const ulonglong2*)&sb1[c];
#pragma unroll
        for (int q = 0; q < 4; q++) { a1[c][q] = bb.x; a1[c + 1][q] = bb.y; }
    }
#pragma unroll
    for (int k = 0; k < 8; k++) {
        u64 r[4];
#pragma unroll
        for (int q = 0; q < 4; q++) r[q] = relu2(a0[k][q]);
#pragma unroll
        for (int c = 0; c < 8; c += 2) {
            const ulonglong2 ww = *(const ulonglong2*)&sw1t[k][c];
#pragma unroll
            for (int q = 0; q < 4; q++) {
                a1[c][q]     = ffma2(ww.x, r[q], a1[c][q]);
                a1[c + 1][q] = ffma2(ww.y, r[q], a1[c + 1][q]);
            }
        }
    }

    // ---- layer 2: relu -> 8 -> 1 ----
    u64 a2[4];
    {
        const u64 b2 = sb2;
#pragma unroll
        for (int q = 0; q < 4; q++) a2[q] = b2;
    }
#pragma unroll
    for (int k = 0; k < 8; k += 2) {
        const ulonglong2 ww = *(const ulonglong2*)&sw2[k];
#pragma unroll
        for (int q = 0; q < 4; q++) {
            a2[q] = ffma2(ww.x, relu2(a1[k][q]), a2[q]);
            a2[q] = ffma2(ww.y, relu2(a1[k + 1][q]), a2[q]);
        }
    }

    float* outp = g_logits + (size_t)inst * HWP;
#pragma unroll
    for (int q = 0; q < 4; q++)
        if (v[q]) *(u64*)(outp + p[q]) = a2[q];
}

// ---------------------------------------------------------------------------
// Kernel B: aligned_bilinear x2 upsample, one 2x4 output block per thread.
// EXACT round-10 version (measured 20.2 us twice, regs=19).
// ---------------------------------------------------------------------------
__global__ void __launch_bounds__(256)
upsample_kernel(float* __restrict__ out)
{
    const int inst = blockIdx.y;
    const int i    = blockIdx.x * 256 + threadIdx.x;
    if (i >= TOTPAIR) return;

    const int r  = i / NPAIR;
    const int j  = i - r * NPAIR;
    const int rm = (r > 0) ? r - 1 : 0;
    const int qm = (j > 0) ? (2 * j - 1) : 0;

    const float* T = g_logits + (size_t)inst * HWP;

    float A1, A2, C1, C2;
    upk2(A1, A2, *(const u64*)(T + rm * WW + 2 * j));
    upk2(C1, C2, *(const u64*)(T + r  * WW + 2 * j));
    const float A0 = T[rm * WW + qm];
    const float C0 = T[r  * WW + qm];

    float4 top, bot;
    top.x = 0.5f * (0.5f * (A0 + A1) + 0.5f * (C0 + C1));
    top.y = 0.5f * (A1 + C1);
    top.z = 0.5f * (0.5f * (A1 + A2) + 0.5f * (C1 + C2));
    top.w = 0.5f * (A2 + C2);
    bot.x = 0.5f * (C0 + C1);
    bot.y = C1;
    bot.z = 0.5f * (C1 + C2);
    bot.w = C2;

    float* ob = out + (size_t)inst * (OH * OW) + (2 * r) * OW + 4 * j;
    *(float4*)ob        = top;
    *(float4*)(ob + OW) = bot;
}

// ---------------------------------------------------------------------------
extern "C" void kernel_launch(void* const* d_in, const int* in_sizes, int n_in,
                              void* d_out, int out_size)
{
    const float* feats  = (const float*)d_in[0];
    const float* params = (const float*)d_in[1];
    const float* ilocs  = (const float*)d_in[2];
    const int*   iminds = (const int*)d_in[3];
    const int*   levels = (const int*)d_in[4];

    int n_inst = in_sizes[1] / NPARAMS;     // 400
    if (n_inst > MAXINST) n_inst = MAXINST;

    dim3 ga((TOTPAIR + 511) / 512, n_inst);   // (15, 400), 128 threads
    logits_kernel<<<ga, 128>>>(feats, params, ilocs, iminds, levels);

    dim3 gb((TOTPAIR + 255) / 256, n_inst);   // (30, 400), 256 threads
    upsample_kernel<<<gb, 256>>>((float*)d_out);
}